// round 6
// baseline (speedup 1.0000x reference)
#include <cuda_runtime.h>
#include <math.h>

// Problem constants
#define NIMG   4
#define HW     48
#define CH     3
#define PLANE  (HW*HW)            // 2304
#define NPIX   (PLANE*CH)         // 6912 per image
#define KS     21
#define KR     10

// Config
#define TPTS   257                // x-grid: t/256, t=0..256
#define GRID   144                // 1 block/SM -> all co-resident, safe spin barrier
#define TB     512
#define YT     4                  // output rows per conv tile (144 = 4n*3c*12)
#define TROWS  (YT + KS - 1)      // 24
#define TCOLS  (HW + KS - 1)      // 68

// Histogram: b-grid step = 1/64 (coarse; linear binning is 2nd-order accurate)
#define BSTEP  64.0f
#define BINS   1408               // covers blur up to ~22
#define NSLICE 36                 // P2 j-slices per image (4 img * 36 = 144 blocks)
#define WSL    40                 // max slice length: ceil(1408/36) = 40
#define STL    420                // tanh window: 257 + 4*40

// Scratch (device globals; no allocation).
__device__ float d_W[NIMG * BINS];          // 5632 floats
__device__ int   d_jmin[NIMG] = {BINS, BINS, BINS, BINS};
__device__ int   d_jmax[NIMG] = {0, 0, 0, 0};
__device__ float d_table[NIMG * TPTS];
__device__ unsigned g_cnt = 0;
__device__ volatile unsigned g_gen = 0;

// Shared pool (floats):
//  persist: IN @0 (1632), KG@1632 KM@1656 KW@1680 (24 ea), M @1704 (192) -> 1896
//  P1: H1 @1896 (1152), H2 @3048 (1152), RED @4200 (32)
//  P2: W @1896 (40), ST @1936 (420)
//  P3: TBL @1896 (260), DF @2156 (1632), H3 @3788 (1152) -> 4940
#define SP_IN   0
#define SP_KG   1632
#define SP_KM   1656
#define SP_KW   1680
#define SP_M    1704
#define SP_H1   1896
#define SP_H2   3048
#define SP_RED  4200
#define SP_W    1896
#define SP_ST   1936
#define SP_TBL  1896
#define SP_DF   2156
#define SP_H3   3788
#define POOL    4960              // 19840 B static smem

__device__ __forceinline__ float frcp(float x) {
    float r;
    asm("rcp.approx.f32 %0, %1;" : "=f"(r) : "f"(x));
    return r;
}
__device__ __forceinline__ float fex2(float x) {
    float r;
    asm("ex2.approx.f32 %0, %1;" : "=f"(r) : "f"(x));
    return r;
}
// tanh(z) = 1 - 2/(1 + e^{2z})
__device__ __forceinline__ float ftanh(float z) {
    float u = fex2(z * 2.8853900817779268f);
    return 1.0f - 2.0f * frcp(1.0f + u);
}

// Grid-wide barrier (monotone generation; all GRID blocks co-resident).
__device__ __forceinline__ void gridbar() {
    __syncthreads();
    __threadfence();
    if (threadIdx.x == 0) {
        unsigned gen = g_gen;
        if (atomicAdd(&g_cnt, 1u) == GRID - 1) {
            g_cnt = 0;
            __threadfence();
            g_gen = gen + 1;
        } else {
            while (g_gen == gen) {}
        }
    }
    __syncthreads();
    __threadfence();
}

// One warp builds a unit-L2 1D Gaussian (2D kernel = exact outer product).
__device__ __forceinline__ void make_k1d(float gamma, float* out) {
    int lane = threadIdx.x & 31;
    float inv2s2 = 0.5f * gamma * gamma;
    const float step = (21.0f / 32.0f) / 20.0f;
    const float mean = 21.0f / 64.0f;
    float v = 0.0f;
    if (lane < KS) {
        float d = (float)lane * step - mean;
        v = expf(-d * d * inv2s2);
    }
    float ss = v * v;
    #pragma unroll
    for (int o = 16; o > 0; o >>= 1) ss += __shfl_xor_sync(0xffffffffu, ss, o);
    if (lane < KS) out[lane] = v * rsqrtf(ss);
}

__global__ __launch_bounds__(TB, 1)
void inrf_fused(const float* __restrict__ in,
                const float* __restrict__ gm,
                const float* __restrict__ gw,
                const float* __restrict__ gg,
                float* __restrict__ out) {
    __shared__ float sp[POOL];

    const int tid  = threadIdx.x;
    const int warp = tid >> 5;
    const int lane = tid & 31;

    // Conv decomposition: 144 = 4n * 3c * 12 ytiles
    const int b   = blockIdx.x;
    const int n   = b / 36;
    const int rem = b % 36;
    const int c   = rem / 12;
    const int y0  = (rem % 12) * YT;

    // ---------------- Phase 1: blur=G(in) -> bin;  M(in) -> smem -----------
    if      (warp == 0) make_k1d(gg[c], sp + SP_KG);
    else if (warp == 1) make_k1d(gm[c], sp + SP_KM);
    else if (warp == 2) make_k1d(gw[c], sp + SP_KW);

    // zero d_table for this replay's P2 accumulation (8 entries per block)
    {
        int i0 = b * 8;
        #pragma unroll
        for (int k = 0; k < 8; k++)
            if (i0 + k < NIMG * TPTS && tid == k) d_table[i0 + k] = 0.0f;
    }

    // zero-padded input tile (rows y0-10..y0+13, cols -10..57), channel c
    for (int i = tid; i < TROWS * TCOLS; i += TB) {
        int r  = i / TCOLS;
        int xc = i % TCOLS - KR;
        int yy = y0 - KR + r;
        float v = 0.0f;
        if ((unsigned)yy < HW && (unsigned)xc < HW)
            v = in[((n * HW + yy) * HW + xc) * CH + c];
        sp[SP_IN + i] = v;
    }
    __syncthreads();

    // taps -> registers
    float tg[KS], tm[KS];
    #pragma unroll
    for (int k = 0; k < KS; k++) { tg[k] = sp[SP_KG + k]; tm[k] = sp[SP_KM + k]; }

    // horizontal pass, both convs
    for (int i = tid; i < TROWS * HW; i += TB) {
        int r = i / HW, x = i % HW;
        const float* row = sp + SP_IN + r * TCOLS + x;
        float s1 = 0.0f, s2 = 0.0f;
        #pragma unroll
        for (int k = 0; k < KS; k++) {
            float v = row[k];
            s1 = fmaf(v, tg[k], s1);
            s2 = fmaf(v, tm[k], s2);
        }
        sp[SP_H1 + i] = s1;
        sp[SP_H2 + i] = s2;
    }
    __syncthreads();

    // vertical pass: bin G-blur (linear weights, 1/64 grid); store M result
    int j0min = BINS, j0max = 0;
    for (int i = tid; i < YT * HW; i += TB) {
        int yo = i / HW, x = i % HW;
        float sg = 0.0f, sm = 0.0f;
        #pragma unroll
        for (int k = 0; k < KS; k++) {
            sg = fmaf(sp[SP_H1 + (yo + k) * HW + x], tg[k], sg);
            sm = fmaf(sp[SP_H2 + (yo + k) * HW + x], tm[k], sm);
        }
        sp[SP_M + i] = sm;
        float u = fminf(fmaxf(sg * BSTEP, 0.0f), (float)(BINS - 2));
        int   j0 = (int)u;
        float w1 = u - (float)j0;
        atomicAdd(&d_W[n * BINS + j0],     1.0f - w1);
        atomicAdd(&d_W[n * BINS + j0 + 1], w1);
        j0min = min(j0min, j0);
        j0max = max(j0max, j0 + 1);
    }
    // block-reduce range trackers -> 1 atomic each per block
    #pragma unroll
    for (int o = 16; o > 0; o >>= 1) {
        j0min = min(j0min, __shfl_xor_sync(0xffffffffu, j0min, o));
        j0max = max(j0max, __shfl_xor_sync(0xffffffffu, j0max, o));
    }
    int* red = (int*)(sp + SP_RED);
    if (lane == 0) { red[warp] = j0min; red[16 + warp] = j0max; }
    __syncthreads();
    if (tid == 0) {
        int mn = BINS, mx = 0;
        #pragma unroll
        for (int w = 0; w < 16; w++) { mn = min(mn, red[w]); mx = max(mx, red[16 + w]); }
        atomicMin(&d_jmin[n], mn);
        atomicMax(&d_jmax[n], mx);
    }

    gridbar();

    // -------- Phase 2: table[t] += sum_{j in slice} W_j tanh(t/256 - j/64) --
    {
        const int n2 = b & 3;
        const int s  = b >> 2;               // slice 0..35
        const int jmin = d_jmin[n2];
        const int jmax = d_jmax[n2];
        const int Wlen = jmax - jmin + 1;
        const int L    = (Wlen + NSLICE - 1) / NSLICE;   // <= 40
        const int js   = jmin + s * L;
        const int je   = min(js + L, jmax + 1);
        const int Ls   = je - js;

        if (Ls > 0) {
            for (int i = tid; i < Ls; i += TB)
                sp[SP_W + i] = d_W[n2 * BINS + js + i];
            // ST[i] = tanh((t - 4j)/256) at i = t + 4*(je-1-j); i < 257+4*(Ls-1)
            const int slen = 257 + 4 * (Ls - 1);
            for (int i = tid; i < slen; i += TB)
                sp[SP_ST + i] = ftanh((float)(i - 4 * (je - 1)) * (1.0f / 256.0f));
            __syncthreads();

            if (warp < 8) {
                const int t = warp * 32 + lane;          // 0..255
                const float* sT = sp + SP_ST + t + 4 * (Ls - 1);
                float a0 = 0.f, a1 = 0.f;
                int ii = 0;
                for (; ii + 1 < Ls; ii += 2) {
                    a0 = fmaf(sp[SP_W + ii],     sT[-4 * ii],     a0);
                    a1 = fmaf(sp[SP_W + ii + 1], sT[-4 * ii - 4], a1);
                }
                if (ii < Ls) a0 = fmaf(sp[SP_W + ii], sT[-4 * ii], a0);
                atomicAdd(&d_table[n2 * TPTS + t], (a0 + a1) * (1.0f / (float)NPIX));
            } else if (warp == 8) {                      // t = 256
                float a = 0.f;
                for (int ii = lane; ii < Ls; ii += 32)
                    a = fmaf(sp[SP_W + ii], sp[SP_ST + 256 + 4 * (Ls - 1 - ii)], a);
                #pragma unroll
                for (int o = 16; o > 0; o >>= 1)
                    a += __shfl_xor_sync(0xffffffffu, a, o);
                if (lane == 0)
                    atomicAdd(&d_table[n2 * TPTS + 256], a * (1.0f / (float)NPIX));
            }
        }
    }

    gridbar();

    // ---------------- Phase 3: out = M - W(diff); re-arm scratch -----------
    // re-zero histogram slices + reset trackers (for the next graph replay)
    {
        int i0 = b * 40;                                // 40*144 >= NIMG*BINS
        for (int i = i0 + tid; i < i0 + 40 && i < NIMG * BINS; i += TB)
            d_W[i] = 0.0f;
        if (b < NIMG && tid == 0) { d_jmin[b] = BINS; d_jmax[b] = 0; }
    }

    for (int i = tid; i < TPTS; i += TB)
        sp[SP_TBL + i] = d_table[n * TPTS + i];
    float tw[KS];
    #pragma unroll
    for (int k = 0; k < KS; k++) tw[k] = sp[SP_KW + k];
    __syncthreads();

    // diff tile from persisted IN tile (zero outside the image)
    for (int i = tid; i < TROWS * TCOLS; i += TB) {
        int r  = i / TCOLS;
        int xc = i % TCOLS - KR;
        int yy = y0 - KR + r;
        float d = 0.0f;
        if ((unsigned)yy < HW && (unsigned)xc < HW) {
            float u = sp[SP_IN + i] * 256.0f;
            u = fminf(fmaxf(u, 0.0f), 255.999f);
            int   i0 = (int)u;
            float fr = u - (float)i0;
            float t0 = sp[SP_TBL + i0], t1 = sp[SP_TBL + i0 + 1];
            d = fmaf(t1 - t0, fr, t0);
        }
        sp[SP_DF + i] = d;
    }
    __syncthreads();

    // horizontal pass (W conv)
    for (int i = tid; i < TROWS * HW; i += TB) {
        int r = i / HW, x = i % HW;
        const float* row = sp + SP_DF + r * TCOLS + x;
        float s = 0.0f;
        #pragma unroll
        for (int k = 0; k < KS; k++) s = fmaf(row[k], tw[k], s);
        sp[SP_H3 + i] = s;
    }
    __syncthreads();

    // vertical pass + final subtraction (L = 1)
    for (int i = tid; i < YT * HW; i += TB) {
        int yo = i / HW, x = i % HW;
        float sw = 0.0f;
        #pragma unroll
        for (int k = 0; k < KS; k++)
            sw = fmaf(sp[SP_H3 + (yo + k) * HW + x], tw[k], sw);
        out[((n * HW + y0 + yo) * HW + x) * CH + c] = sp[SP_M + i] - sw;
    }
}

extern "C" void kernel_launch(void* const* d_in, const int* in_sizes, int n_in,
                              void* d_out, int out_size) {
    const float* in = (const float*)d_in[0];
    const float* gm = (const float*)d_in[1];
    const float* gw = (const float*)d_in[2];
    const float* gg = (const float*)d_in[3];
    float* out = (float*)d_out;

    inrf_fused<<<GRID, TB>>>(in, gm, gw, gg, out);
}

// round 7
// speedup vs baseline: 1.0114x; 1.0114x over previous
#include <cuda_runtime.h>
#include <math.h>

// Problem constants
#define NIMG   4
#define HW     48
#define CH     3
#define PLANE  (HW*HW)            // 2304
#define NPIX   (PLANE*CH)         // 6912 per image
#define KS     21
#define KR     10

// Config
#define TPTS   257                // x-grid: t/256, t=0..256
#define GRID   144                // 1 block/SM -> all co-resident, safe spin barriers
#define TB     512
#define YT     4                  // output rows per conv tile (144 = 4n*3c*12)
#define TROWS  (YT + KS - 1)      // 24
#define TCOLS  (HW + KS - 1)      // 68
#define BPI    36                 // blocks per image

// Histogram: b-grid step = 1/64 (linear binning, 2nd-order accurate)
#define BSTEP  64.0f
#define BINS   1408               // covers blur up to ~22

// Scratch (device globals; no allocation).
__device__ float d_W[NIMG * BINS];
__device__ int   d_jmin[NIMG] = {BINS, BINS, BINS, BINS};
__device__ int   d_jmax[NIMG] = {0, 0, 0, 0};
__device__ float d_table[NIMG * TPTS];
__device__ unsigned g_cnt2[2 * NIMG];
__device__ unsigned g_gen2[2 * NIMG];

// Shared pool (floats):
//  persist: IN @0 (1632), KG@1632 KM@1656 KW@1680 (24 ea), M @1704 (192)
//  P1: H1 @1896 (1152), H2 @3048 (1152)
//  P2: W @1896 (40), ST @1936 (<=413)
//  P3: TBL @1896 (260), DF @2156 (1632), H3 @3788 (1152)
#define SP_IN   0
#define SP_KG   1632
#define SP_KM   1656
#define SP_KW   1680
#define SP_M    1704
#define SP_H1   1896
#define SP_H2   3048
#define SP_W    1896
#define SP_ST   1936
#define SP_TBL  1896
#define SP_DF   2156
#define SP_H3   3788
#define POOL    4960              // 19840 B static smem

__device__ __forceinline__ float frcp(float x) {
    float r; asm("rcp.approx.f32 %0, %1;" : "=f"(r) : "f"(x)); return r;
}
__device__ __forceinline__ float fex2(float x) {
    float r; asm("ex2.approx.f32 %0, %1;" : "=f"(r) : "f"(x)); return r;
}
// tanh(z) = 1 - 2/(1 + e^{2z})
__device__ __forceinline__ float ftanh(float z) {
    float u = fex2(z * 2.8853900817779268f);
    return 1.0f - 2.0f * frcp(1.0f + u);
}

// f32x2 packed helpers (FFMA2 path: only reachable via PTX fma.rn.f32x2)
__device__ __forceinline__ unsigned long long pack2(float lo, float hi) {
    unsigned long long d;
    asm("mov.b64 %0, {%1, %2};" : "=l"(d) : "r"(__float_as_uint(lo)), "r"(__float_as_uint(hi)));
    return d;
}
__device__ __forceinline__ void unpack2(unsigned long long v, float& lo, float& hi) {
    unsigned a, b;
    asm("mov.b64 {%0, %1}, %2;" : "=r"(a), "=r"(b) : "l"(v));
    lo = __uint_as_float(a); hi = __uint_as_float(b);
}
__device__ __forceinline__ void fma2(unsigned long long& acc,
                                     unsigned long long a, unsigned long long b) {
    asm("fma.rn.f32x2 %0, %1, %2, %0;" : "+l"(acc) : "l"(a), "l"(b));
}

// Per-image spin barrier (monotone generation; 36 co-resident blocks/image).
__device__ __forceinline__ void imgbar(int idx) {
    __syncthreads();
    __threadfence();
    if (threadIdx.x == 0) {
        volatile unsigned* vgen = (volatile unsigned*)&g_gen2[idx];
        unsigned gen = *vgen;
        if (atomicAdd(&g_cnt2[idx], 1u) == BPI - 1) {
            g_cnt2[idx] = 0;
            __threadfence();
            *vgen = gen + 1;
        } else {
            while (*vgen == gen) {}
        }
    }
    __syncthreads();
    __threadfence();
}

// One warp builds a unit-L2 1D Gaussian (2D kernel = exact outer product).
__device__ __forceinline__ void make_k1d(float gamma, float* out) {
    int lane = threadIdx.x & 31;
    float inv2s2 = 0.5f * gamma * gamma;
    const float step = (21.0f / 32.0f) / 20.0f;
    const float mean = 21.0f / 64.0f;
    float v = 0.0f;
    if (lane < KS) {
        float d = (float)lane * step - mean;
        v = expf(-d * d * inv2s2);
    }
    float ss = v * v;
    #pragma unroll
    for (int o = 16; o > 0; o >>= 1) ss += __shfl_xor_sync(0xffffffffu, ss, o);
    if (lane < KS) out[lane] = v * rsqrtf(ss);
}

__global__ __launch_bounds__(TB, 1)
void inrf_fused(const float* __restrict__ in,
                const float* __restrict__ gm,
                const float* __restrict__ gw,
                const float* __restrict__ gg,
                float* __restrict__ out) {
    __shared__ float sp[POOL];

    const int tid  = threadIdx.x;
    const int warp = tid >> 5;
    const int lane = tid & 31;

    // Decomposition: 144 = 4n * 36; within image: 3c * 12 ytiles
    const int b   = blockIdx.x;
    const int n   = b / BPI;
    const int rem = b % BPI;          // also this block's P2 slice id
    const int c   = rem / 12;
    const int y0  = (rem % 12) * YT;

    // ---------------- Phase 1: blur=G(in) -> bin;  M(in) -> smem -----------
    if      (warp == 0) make_k1d(gg[c], sp + SP_KG);
    else if (warp == 1) make_k1d(gm[c], sp + SP_KM);
    else if (warp == 2) make_k1d(gw[c], sp + SP_KW);

    // zero OWN image's table slice for this replay's P2 accumulation
    {
        int i0 = rem * 8;                      // 36*8 = 288 >= 257
        if (tid < 8 && i0 + tid < TPTS) d_table[n * TPTS + i0 + tid] = 0.0f;
    }

    // zero-padded input tile (rows y0-10..y0+13, cols -10..57), channel c
    for (int i = tid; i < TROWS * TCOLS; i += TB) {
        int r  = i / TCOLS;
        int xc = i % TCOLS - KR;
        int yy = y0 - KR + r;
        float v = 0.0f;
        if ((unsigned)yy < HW && (unsigned)xc < HW)
            v = in[((n * HW + yy) * HW + xc) * CH + c];
        sp[SP_IN + i] = v;
    }
    __syncthreads();

    // packed taps (lo=G, hi=M) -> registers
    unsigned long long tk[KS];
    #pragma unroll
    for (int k = 0; k < KS; k++) tk[k] = pack2(sp[SP_KG + k], sp[SP_KM + k]);

    // horizontal pass, both convs via packed f32x2 FMA
    for (int i = tid; i < TROWS * HW; i += TB) {
        int r = i / HW, x = i % HW;
        const float* row = sp + SP_IN + r * TCOLS + x;
        unsigned long long acc = 0ull;
        #pragma unroll
        for (int k = 0; k < KS; k++) {
            float v = row[k];
            fma2(acc, pack2(v, v), tk[k]);
        }
        float s1, s2; unpack2(acc, s1, s2);
        sp[SP_H1 + i] = s1;                    // G partial
        sp[SP_H2 + i] = s2;                    // M partial
    }
    __syncthreads();

    // vertical pass: bin G-blur (linear weights, 1/64 grid); store M result
    int j0min = BINS, j0max = 0;
    for (int i = tid; i < YT * HW; i += TB) {
        int yo = i / HW, x = i % HW;
        unsigned long long acc = 0ull;
        #pragma unroll
        for (int k = 0; k < KS; k++) {
            int o = (yo + k) * HW + x;
            fma2(acc, pack2(sp[SP_H1 + o], sp[SP_H2 + o]), tk[k]);
        }
        float sg, sm; unpack2(acc, sg, sm);
        sp[SP_M + i] = sm;
        float u = fminf(fmaxf(sg * BSTEP, 0.0f), (float)(BINS - 2));
        int   j0 = (int)u;
        float w1 = u - (float)j0;
        atomicAdd(&d_W[n * BINS + j0],     1.0f - w1);
        atomicAdd(&d_W[n * BINS + j0 + 1], w1);
        j0min = min(j0min, j0);
        j0max = max(j0max, j0 + 1);
    }
    // per-warp reduce -> direct RED (no block sync / serial tail)
    if (warp < 6) {
        #pragma unroll
        for (int o = 16; o > 0; o >>= 1) {
            j0min = min(j0min, __shfl_xor_sync(0xffffffffu, j0min, o));
            j0max = max(j0max, __shfl_xor_sync(0xffffffffu, j0max, o));
        }
        if (lane == 0) {
            atomicMin(&d_jmin[n], j0min);
            atomicMax(&d_jmax[n], j0max);
        }
    }

    imgbar(n);                                 // image-local barrier #1

    // -------- Phase 2: table[t] += sum_{j in slice} W_j tanh(t/256 - j/64) --
    {
        const int s    = rem;                  // slice 0..35 of OWN image
        const int jmin = d_jmin[n];
        const int jmax = d_jmax[n];
        const int Wlen = jmax - jmin + 1;
        const int L    = (Wlen + BPI - 1) / BPI;   // <= 40
        const int js   = jmin + s * L;
        const int je   = min(js + L, jmax + 1);
        const int Ls   = je - js;

        if (Ls > 0) {
            for (int i = tid; i < Ls; i += TB)
                sp[SP_W + i] = d_W[n * BINS + js + i];
            // ST[i] = tanh((t - 4j)/256) at i = t + 4*(je-1-j)
            const int slen = 257 + 4 * (Ls - 1);
            for (int i = tid; i < slen; i += TB)
                sp[SP_ST + i] = ftanh((float)(i - 4 * (je - 1)) * (1.0f / 256.0f));
            __syncthreads();

            if (warp < 8) {
                const int t = warp * 32 + lane;            // 0..255
                const float* sT = sp + SP_ST + t + 4 * (Ls - 1);
                float a0 = 0.f, a1 = 0.f;
                int ii = 0;
                for (; ii + 1 < Ls; ii += 2) {
                    a0 = fmaf(sp[SP_W + ii],     sT[-4 * ii],     a0);
                    a1 = fmaf(sp[SP_W + ii + 1], sT[-4 * ii - 4], a1);
                }
                if (ii < Ls) a0 = fmaf(sp[SP_W + ii], sT[-4 * ii], a0);
                atomicAdd(&d_table[n * TPTS + t], (a0 + a1) * (1.0f / (float)NPIX));
            } else if (warp == 8) {                        // t = 256
                float a = 0.f;
                for (int ii = lane; ii < Ls; ii += 32)
                    a = fmaf(sp[SP_W + ii], sp[SP_ST + 256 + 4 * (Ls - 1 - ii)], a);
                #pragma unroll
                for (int o = 16; o > 0; o >>= 1)
                    a += __shfl_xor_sync(0xffffffffu, a, o);
                if (lane == 0)
                    atomicAdd(&d_table[n * TPTS + 256], a * (1.0f / (float)NPIX));
            }
        }
    }

    imgbar(NIMG + n);                          // image-local barrier #2

    // ---------------- Phase 3: out = M - W(diff); re-arm scratch -----------
    // re-zero OWN image's histogram slice + reset trackers (next replay)
    {
        int i0 = rem * 40;                     // 40*36 = 1440 >= BINS
        for (int i = i0 + tid; i < i0 + 40 && i < BINS; i += TB)
            d_W[n * BINS + i] = 0.0f;
        if (rem == 0 && tid == 0) { d_jmin[n] = BINS; d_jmax[n] = 0; }
    }

    for (int i = tid; i < TPTS; i += TB)
        sp[SP_TBL + i] = d_table[n * TPTS + i];
    float tw[KS];
    #pragma unroll
    for (int k = 0; k < KS; k++) tw[k] = sp[SP_KW + k];
    __syncthreads();

    // diff tile from persisted IN tile (zero outside the image)
    for (int i = tid; i < TROWS * TCOLS; i += TB) {
        int r  = i / TCOLS;
        int xc = i % TCOLS - KR;
        int yy = y0 - KR + r;
        float d = 0.0f;
        if ((unsigned)yy < HW && (unsigned)xc < HW) {
            float u = sp[SP_IN + i] * 256.0f;
            u = fminf(fmaxf(u, 0.0f), 255.999f);
            int   i0 = (int)u;
            float fr = u - (float)i0;
            float t0 = sp[SP_TBL + i0], t1 = sp[SP_TBL + i0 + 1];
            d = fmaf(t1 - t0, fr, t0);
        }
        sp[SP_DF + i] = d;
    }
    __syncthreads();

    // horizontal pass (W conv)
    for (int i = tid; i < TROWS * HW; i += TB) {
        int r = i / HW, x = i % HW;
        const float* row = sp + SP_DF + r * TCOLS + x;
        float s = 0.0f;
        #pragma unroll
        for (int k = 0; k < KS; k++) s = fmaf(row[k], tw[k], s);
        sp[SP_H3 + i] = s;
    }
    __syncthreads();

    // vertical pass + final subtraction (L = 1)
    for (int i = tid; i < YT * HW; i += TB) {
        int yo = i / HW, x = i % HW;
        float sw = 0.0f;
        #pragma unroll
        for (int k = 0; k < KS; k++)
            sw = fmaf(sp[SP_H3 + (yo + k) * HW + x], tw[k], sw);
        out[((n * HW + y0 + yo) * HW + x) * CH + c] = sp[SP_M + i] - sw;
    }
}

extern "C" void kernel_launch(void* const* d_in, const int* in_sizes, int n_in,
                              void* d_out, int out_size) {
    const float* in = (const float*)d_in[0];
    const float* gm = (const float*)d_in[1];
    const float* gw = (const float*)d_in[2];
    const float* gg = (const float*)d_in[3];
    float* out = (float*)d_out;

    inrf_fused<<<GRID, TB>>>(in, gm, gw, gg, out);
}

// round 8
// speedup vs baseline: 1.3088x; 1.2941x over previous
#include <cuda_runtime.h>
#include <math.h>

// Problem constants
#define NIMG   4
#define HW     48
#define CH     3
#define NPIX   6912              // per image
#define KS     21
#define KR     10

// Config
#define TPTS   129               // x-grid: t/128, t=0..128
#define GRID   144               // 1 block/SM -> all co-resident, safe spin barrier
#define TB     512
#define YT     4                 // output rows per conv tile (144 = 4n*3c*12)
#define TROWS  (YT + KS - 1)     // 24
#define TCOLS  (HW + KS - 1)     // 68
#define BPI    36                // blocks per image

// Scratch (device globals; no allocation). d_part is overwritten each run.
__device__ float d_part[NIMG][BPI][TPTS];
__device__ unsigned g_cntb[NIMG];
__device__ unsigned g_genb[NIMG];

// Shared pool (floats):
//  persist: IN @0 (1632), KG@1632 KM@1656 KW@1680 (24 ea), M @1704 (192)
//  P1: F @1896 (192), H1 @2088 (1152), H2 @3240 (1152); PRT @2088 (387, reuses H1)
//  P3: TBL @2088 (129), DF @2220 (1632), H3 @3852 (1152)
#define SP_IN   0
#define SP_KG   1632
#define SP_KM   1656
#define SP_KW   1680
#define SP_M    1704
#define SP_F    1896
#define SP_H1   2088
#define SP_H2   3240
#define SP_PRT  2088
#define SP_TBL  2088
#define SP_DF   2220
#define SP_H3   3852
#define POOL    5008             // 20032 B static smem

__device__ __forceinline__ float frcp(float x) {
    float r; asm("rcp.approx.f32 %0, %1;" : "=f"(r) : "f"(x)); return r;
}

// f32x2 packed helpers (FFMA2 via PTX fma.rn.f32x2)
__device__ __forceinline__ unsigned long long pack2(float lo, float hi) {
    unsigned long long d;
    asm("mov.b64 %0, {%1, %2};" : "=l"(d) : "r"(__float_as_uint(lo)), "r"(__float_as_uint(hi)));
    return d;
}
__device__ __forceinline__ void unpack2(unsigned long long v, float& lo, float& hi) {
    unsigned a, b;
    asm("mov.b64 {%0, %1}, %2;" : "=r"(a), "=r"(b) : "l"(v));
    lo = __uint_as_float(a); hi = __uint_as_float(b);
}
__device__ __forceinline__ void fma2(unsigned long long& acc,
                                     unsigned long long a, unsigned long long b) {
    asm("fma.rn.f32x2 %0, %1, %2, %0;" : "+l"(acc) : "l"(a), "l"(b));
}

// Per-image spin barrier (monotone generation; 36 co-resident blocks/image).
__device__ __forceinline__ void imgbar(int idx) {
    __syncthreads();
    __threadfence();
    if (threadIdx.x == 0) {
        volatile unsigned* vgen = (volatile unsigned*)&g_genb[idx];
        unsigned gen = *vgen;
        if (atomicAdd(&g_cntb[idx], 1u) == BPI - 1) {
            g_cntb[idx] = 0;
            __threadfence();
            *vgen = gen + 1;
        } else {
            while (*vgen == gen) {}
        }
    }
    __syncthreads();
    __threadfence();
}

// One warp builds a unit-L2 1D Gaussian (2D kernel = exact outer product).
__device__ __forceinline__ void make_k1d(float gamma, float* out) {
    int lane = threadIdx.x & 31;
    float inv2s2 = 0.5f * gamma * gamma;
    const float step = (21.0f / 32.0f) / 20.0f;
    const float mean = 21.0f / 64.0f;
    float v = 0.0f;
    if (lane < KS) {
        float d = (float)lane * step - mean;
        v = expf(-d * d * inv2s2);
    }
    float ss = v * v;
    #pragma unroll
    for (int o = 16; o > 0; o >>= 1) ss += __shfl_xor_sync(0xffffffffu, ss, o);
    if (lane < KS) out[lane] = v * rsqrtf(ss);
}

__global__ __launch_bounds__(TB, 1)
void inrf_fused(const float* __restrict__ in,
                const float* __restrict__ gm,
                const float* __restrict__ gw,
                const float* __restrict__ gg,
                float* __restrict__ out) {
    __shared__ float sp[POOL];

    const int tid  = threadIdx.x;
    const int warp = tid >> 5;

    // Decomposition: 144 = 4n * 36; within image: 3c * 12 ytiles
    const int b   = blockIdx.x;
    const int n   = b / BPI;
    const int rem = b % BPI;
    const int c   = rem / 12;
    const int y0  = (rem % 12) * YT;

    // ---------------- Phase 1: convs + per-block partial tanh-table --------
    if      (warp == 0) make_k1d(gg[c], sp + SP_KG);
    else if (warp == 1) make_k1d(gm[c], sp + SP_KM);
    else if (warp == 2) make_k1d(gw[c], sp + SP_KW);

    // zero-padded input tile (rows y0-10..y0+13, cols -10..57), channel c
    for (int i = tid; i < TROWS * TCOLS; i += TB) {
        int r  = i / TCOLS;
        int xc = i % TCOLS - KR;
        int yy = y0 - KR + r;
        float v = 0.0f;
        if ((unsigned)yy < HW && (unsigned)xc < HW)
            v = in[((n * HW + yy) * HW + xc) * CH + c];
        sp[SP_IN + i] = v;
    }
    __syncthreads();

    // packed taps (lo=G, hi=M) -> registers
    unsigned long long tk[KS];
    #pragma unroll
    for (int k = 0; k < KS; k++) tk[k] = pack2(sp[SP_KG + k], sp[SP_KM + k]);

    // horizontal pass, both convs (packed f32x2 FMA)
    for (int i = tid; i < TROWS * HW; i += TB) {
        int r = i / HW, x = i % HW;
        const float* row = sp + SP_IN + r * TCOLS + x;
        unsigned long long acc = 0ull;
        #pragma unroll
        for (int k = 0; k < KS; k++) {
            float v = row[k];
            fma2(acc, pack2(v, v), tk[k]);
        }
        float s1, s2; unpack2(acc, s1, s2);
        sp[SP_H1 + i] = s1;                    // G partial
        sp[SP_H2 + i] = s2;                    // M partial
    }
    __syncthreads();

    // vertical pass: M -> smem;  F = exp(-2*blur) -> smem
    if (tid < YT * HW) {
        int yo = tid / HW, x = tid % HW;
        unsigned long long acc = 0ull;
        #pragma unroll
        for (int k = 0; k < KS; k++) {
            int o = (yo + k) * HW + x;
            fma2(acc, pack2(sp[SP_H1 + o], sp[SP_H2 + o]), tk[k]);
        }
        float sg, sm; unpack2(acc, sg, sm);
        sp[SP_M + tid] = sm;
        sp[SP_F + tid] = __expf(-2.0f * sg);
    }
    __syncthreads();

    // partial table: prt[t*3+part] = sum over 64 of this block's 192 F values
    // of 1/(1 + e^{2 t/128} * F).  (387 threads; part-interleaved -> no bank
    // conflicts: 3 distinct banks + broadcast within each part group)
    if (tid < 3 * TPTS) {
        int t    = tid / 3;
        int part = tid - 3 * t;
        float E = __expf((float)t * (2.0f / 128.0f));
        float a0 = 0.f, a1 = 0.f, a2 = 0.f, a3 = 0.f;
        #pragma unroll 4
        for (int k = 0; k < 64; k += 4) {
            a0 += frcp(fmaf(E, sp[SP_F + part + 3 * k],     1.0f));
            a1 += frcp(fmaf(E, sp[SP_F + part + 3 * k + 3], 1.0f));
            a2 += frcp(fmaf(E, sp[SP_F + part + 3 * k + 6], 1.0f));
            a3 += frcp(fmaf(E, sp[SP_F + part + 3 * k + 9], 1.0f));
        }
        sp[SP_PRT + tid] = (a0 + a1) + (a2 + a3);
    }
    __syncthreads();

    // write this block's 129-entry partial row (plain store, replay-safe)
    if (tid < TPTS)
        d_part[n][rem][tid] = sp[SP_PRT + 3 * tid] + sp[SP_PRT + 3 * tid + 1]
                            + sp[SP_PRT + 3 * tid + 2];

    imgbar(n);                                 // single per-image barrier

    // ---------------- Phase 3: reduce table; out = M - W(diff) -------------
    if (tid < TPTS) {
        const float* p = &d_part[n][0][tid];
        float a0 = 0.f, a1 = 0.f, a2 = 0.f, a3 = 0.f;
        #pragma unroll
        for (int s = 0; s < BPI; s += 4) {
            a0 += p[(s + 0) * TPTS];
            a1 += p[(s + 1) * TPTS];
            a2 += p[(s + 2) * TPTS];
            a3 += p[(s + 3) * TPTS];
        }
        sp[SP_TBL + tid] = 1.0f - ((a0 + a1) + (a2 + a3)) * (2.0f / (float)NPIX);
    }
    float tw[KS];
    #pragma unroll
    for (int k = 0; k < KS; k++) tw[k] = sp[SP_KW + k];
    __syncthreads();

    // diff tile from persisted IN tile (zero outside the image)
    for (int i = tid; i < TROWS * TCOLS; i += TB) {
        int r  = i / TCOLS;
        int xc = i % TCOLS - KR;
        int yy = y0 - KR + r;
        float d = 0.0f;
        if ((unsigned)yy < HW && (unsigned)xc < HW) {
            float u = sp[SP_IN + i] * 128.0f;
            u = fminf(fmaxf(u, 0.0f), 127.999f);
            int   i0 = (int)u;
            float fr = u - (float)i0;
            float t0 = sp[SP_TBL + i0], t1 = sp[SP_TBL + i0 + 1];
            d = fmaf(t1 - t0, fr, t0);
        }
        sp[SP_DF + i] = d;
    }
    __syncthreads();

    // horizontal pass (W conv)
    for (int i = tid; i < TROWS * HW; i += TB) {
        int r = i / HW, x = i % HW;
        const float* row = sp + SP_DF + r * TCOLS + x;
        float s = 0.0f;
        #pragma unroll
        for (int k = 0; k < KS; k++) s = fmaf(row[k], tw[k], s);
        sp[SP_H3 + i] = s;
    }
    __syncthreads();

    // vertical pass + final subtraction (L = 1)
    if (tid < YT * HW) {
        int yo = tid / HW, x = tid % HW;
        float sw = 0.0f;
        #pragma unroll
        for (int k = 0; k < KS; k++)
            sw = fmaf(sp[SP_H3 + (yo + k) * HW + x], tw[k], sw);
        out[((n * HW + y0 + yo) * HW + x) * CH + c] = sp[SP_M + tid] - sw;
    }
}

extern "C" void kernel_launch(void* const* d_in, const int* in_sizes, int n_in,
                              void* d_out, int out_size) {
    const float* in = (const float*)d_in[0];
    const float* gm = (const float*)d_in[1];
    const float* gw = (const float*)d_in[2];
    const float* gg = (const float*)d_in[3];
    float* out = (float*)d_out;

    inrf_fused<<<GRID, TB>>>(in, gm, gw, gg, out);
}